// round 10
// baseline (speedup 1.0000x reference)
#include <cuda_runtime.h>
#include <cuda_bf16.h>
#include <math.h>
#include <stdint.h>

#define NN 100000
#define EE 3200000
#define KITER 10
#define ALPHAF 0.1f
#define EPSB 1e-5f
#define NBLK_SCAN 196
#define TM 64
#define NTILES ((NN + TM - 1) / TM)
#define FGRID 888

// ---- smem layout (bytes) ----
#define SA 40
#define SH 136
#define A_CHUNK_B (64 * SA * 2)
#define W_CHUNK_B (128 * SA * 2)
#define OFF_A    0
#define OFF_W    (OFF_A + 4 * A_CHUNK_B)
#define OFF_H1HI (OFF_W + 4 * W_CHUNK_B)
#define OFF_H1LO (OFF_H1HI + 64 * SH * 2)
#define OFF_PART (OFF_H1LO + 64 * SH * 2)
#define OFF_B1   (OFF_PART + 3072)
#define OFF_B2   (OFF_B1 + 512)
#define OFF_W3   (OFF_B2 + 512)
#define OFF_B3   (OFF_W3 + 1536)
#define SMEM_MLP (OFF_B3 + 16)

#define AHI_OFF(b) (OFF_A + (b) * A_CHUNK_B)
#define ALO_OFF(b) (OFF_A + 2 * A_CHUNK_B + (b) * A_CHUNK_B)
#define WHI_OFF(b) (OFF_W + (b) * W_CHUNK_B)
#define WLO_OFF(b) (OFF_W + 2 * W_CHUNK_B + (b) * W_CHUNK_B)

// ---------------- device scratch ----------------
__device__ __nv_bfloat16 g_w1hi[128 * 512], g_w1lo[128 * 512];
__device__ __nv_bfloat16 g_w2hi[128 * 128], g_w2lo[128 * 128];
__device__ float g_b1e[128], g_b2e[128];
__device__ float4 g_h0a[NN];   // alpha * h0
__device__ float4 g_yA[NN];    // y ping
__device__ float4 g_yB[NN];    // y pong; raw h0 from mlp
__device__ float g_dinv[NN];
__device__ int g_cnt[NN];
__device__ int g_rowptr[NN + 1];
__device__ int g_wp[NN];
__device__ int g_col[EE];
__device__ unsigned long long g_desc[NBLK_SCAN];
__device__ volatile unsigned g_count0;
__device__ volatile unsigned g_sense0;

// ---------------- helpers ----------------
__device__ __forceinline__ uint32_t smem_u32(const void* p) {
    uint32_t a;
    asm("{ .reg .u64 t; cvta.to.shared.u64 t, %1; cvt.u32.u64 %0, t; }" : "=r"(a) : "l"(p));
    return a;
}
__device__ __forceinline__ uint16_t bfbits(__nv_bfloat16 h) { __nv_bfloat16_raw r = h; return r.x; }
__device__ __forceinline__ uint32_t pk2(__nv_bfloat16 a, __nv_bfloat16 b) {
    return (uint32_t)bfbits(a) | ((uint32_t)bfbits(b) << 16);
}
__device__ __forceinline__ float bflo(uint32_t u) { return __uint_as_float(u << 16); }
__device__ __forceinline__ float bfhi(uint32_t u) { return __uint_as_float(u & 0xFFFF0000u); }

__device__ __forceinline__ void cp16(uint32_t dst, const void* src) {
    asm volatile("cp.async.cg.shared.global [%0], [%1], 16;" :: "r"(dst), "l"(src));
}
#define CP_COMMIT() asm volatile("cp.async.commit_group;" ::: "memory")
#define CP_WAIT0()  asm volatile("cp.async.wait_group 0;" ::: "memory")
#define CP_WAIT1()  asm volatile("cp.async.wait_group 1;" ::: "memory")

__device__ __forceinline__ void ldsm4(uint32_t r[4], uint32_t a) {
    asm volatile("ldmatrix.sync.aligned.m8n8.x4.shared.b16 {%0,%1,%2,%3}, [%4];"
        : "=r"(r[0]), "=r"(r[1]), "=r"(r[2]), "=r"(r[3]) : "r"(a));
}
__device__ __forceinline__ void mma16816(float c[4], const uint32_t a[4], uint32_t b0, uint32_t b1) {
    asm volatile("mma.sync.aligned.m16n8k16.row.col.f32.bf16.bf16.f32 "
        "{%0,%1,%2,%3}, {%4,%5,%6,%7}, {%8,%9}, {%0,%1,%2,%3};"
        : "+f"(c[0]), "+f"(c[1]), "+f"(c[2]), "+f"(c[3])
        : "r"(a[0]), "r"(a[1]), "r"(a[2]), "r"(a[3]), "r"(b0), "r"(b1));
}

__device__ __forceinline__ void stcg4(float4* p, float4 v) {
    asm volatile("st.global.cg.v4.f32 [%0], {%1,%2,%3,%4};"
        :: "l"(p), "f"(v.x), "f"(v.y), "f"(v.z), "f"(v.w));
}

// sense-reversing grid barrier; __threadfence (gpu scope) also invalidates L1 (CCTL.IVALL),
// making plain __ldg on y safe across iterations. Even total flips -> self-resetting.
__device__ __forceinline__ void gbar(unsigned s) {
    __syncthreads();
    __threadfence();
    if (threadIdx.x == 0) {
        if (atomicAdd((unsigned*)&g_count0, 1u) == FGRID - 1) {
            g_count0 = 0;
            __threadfence();
            g_sense0 = s;
        } else {
            while (g_sense0 != s) { }
        }
    }
    __syncthreads();
}

// one K=32 chunk of split-2 MMA, warp tile M32 x N32
__device__ __forceinline__ void mma_chunk32(uint32_t sb, int a_hi_off, int a_lo_off, int a_stride,
                                            int a_kcol, int w_hi_off, int w_lo_off,
                                            float acc[2][4][4], int wm, int wn, int lane) {
    const int arow = (lane & 15);
    const int asel = (lane >> 4) & 1;
    const int seg = lane >> 3;
    const int b_nrow = (seg >> 1) * 8 + (lane & 7);
    const int b_kofs = (seg & 1) * 8;
#pragma unroll
    for (int ks = 0; ks < 2; ks++) {
        const int k0a = a_kcol + ks * 16;
        const int k0w = ks * 16;
        uint32_t ah[2][4], al[2][4];
#pragma unroll
        for (int mi = 0; mi < 2; mi++) {
            const int row = wm * 32 + mi * 16 + arow;
            ldsm4(ah[mi], sb + a_hi_off + (row * a_stride + k0a + asel * 8) * 2);
            ldsm4(al[mi], sb + a_lo_off + (row * a_stride + k0a + asel * 8) * 2);
        }
#pragma unroll
        for (int ni2 = 0; ni2 < 2; ni2++) {
            const int nrow = wn * 32 + ni2 * 16 + b_nrow;
            uint32_t bh[4], bl[4];
            ldsm4(bh, sb + w_hi_off + (nrow * SA + k0w + b_kofs) * 2);
            ldsm4(bl, sb + w_lo_off + (nrow * SA + k0w + b_kofs) * 2);
#pragma unroll
            for (int h = 0; h < 2; h++) {
                const int ni = ni2 * 2 + h;
#pragma unroll
                for (int mi = 0; mi < 2; mi++) {
                    mma16816(acc[mi][ni], ah[mi], bh[2 * h], bh[2 * h + 1]);
                    mma16816(acc[mi][ni], ah[mi], bl[2 * h], bl[2 * h + 1]);
                    mma16816(acc[mi][ni], al[mi], bh[2 * h], bh[2 * h + 1]);
                }
            }
        }
    }
}

// ---------------- hist (+ desc clear) ----------------
__global__ void hist_kernel(const int* __restrict__ ei) {
    int gt = blockIdx.x * blockDim.x + threadIdx.x;
    if (gt < NBLK_SCAN) g_desc[gt] = 0ULL;
    if (gt < EE / 4) {
        int4 d = ((const int4*)(ei + EE))[gt];
        atomicAdd(&g_cnt[d.x], 1);
        atomicAdd(&g_cnt[d.y], 1);
        atomicAdd(&g_cnt[d.z], 1);
        atomicAdd(&g_cnt[d.w], 1);
    }
}

// ---------------- weight prep (runs on side stream) ----------------
__global__ void prepw_kernel(const float* __restrict__ w1, const float* __restrict__ b1,
                             const float* __restrict__ g1, const float* __restrict__ be1,
                             const float* __restrict__ m1, const float* __restrict__ v1,
                             const float* __restrict__ w2, const float* __restrict__ b2,
                             const float* __restrict__ g2, const float* __restrict__ be2,
                             const float* __restrict__ m2, const float* __restrict__ v2) {
    int j = blockIdx.x;
    float s1 = g1[j] * rsqrtf(v1[j] + EPSB);
    float s2 = g2[j] * rsqrtf(v2[j] + EPSB);
    for (int k = threadIdx.x; k < 512; k += blockDim.x) {
        float w = s1 * w1[j * 512 + k];
        __nv_bfloat16 h = __float2bfloat16(w);
        g_w1hi[j * 512 + k] = h;
        g_w1lo[j * 512 + k] = __float2bfloat16(w - __bfloat162float(h));
    }
    for (int k = threadIdx.x; k < 128; k += blockDim.x) {
        float w = s2 * w2[j * 128 + k];
        __nv_bfloat16 h = __float2bfloat16(w);
        g_w2hi[j * 128 + k] = h;
        g_w2lo[j * 128 + k] = __float2bfloat16(w - __bfloat162float(h));
    }
    if (threadIdx.x == 0) {
        g_b1e[j] = s1 * (b1[j] - m1[j]) + be1[j];
        g_b2e[j] = s2 * (b2[j] - m2[j]) + be2[j];
    }
}

// ---------------- decoupled-lookback scan (+ cnt re-zero) ----------------
__global__ __launch_bounds__(512) void scan_kernel() {
    __shared__ int s[512];
    __shared__ int s_run;
    const int tid = threadIdx.x, bid = blockIdx.x;
    const int idx = bid * 512 + tid;
    const int v = (idx < NN) ? g_cnt[idx] : 0;
    s[tid] = v;
    __syncthreads();
    for (int off = 1; off < 512; off <<= 1) {
        int t = (tid >= off) ? s[tid - off] : 0;
        __syncthreads();
        s[tid] += t;
        __syncthreads();
    }
    const int agg = s[511];
    if (tid == 0) {
        unsigned long long d = (bid == 0) ? ((2ULL << 32) | (unsigned)agg)
                                          : ((1ULL << 32) | (unsigned)agg);
        atomicExch(&g_desc[bid], d);
        if (bid == 0) s_run = 0;
    }
    if (bid > 0 && tid < 32) {
        int run = 0;
        int j = bid - 1;
        while (true) {
            int ridx = j - tid;
            unsigned long long d = (ridx >= 0) ? atomicAdd(&g_desc[ridx], 0ULL) : (2ULL << 32);
            int st = (int)(d >> 32);
            int val = (int)(d & 0xffffffffu);
            unsigned inv  = __ballot_sync(0xffffffffu, st == 0);
            unsigned incl = __ballot_sync(0xffffffffu, st == 2);
            int fInv  = inv  ? (__ffs(inv) - 1)  : 32;
            int fIncl = incl ? (__ffs(incl) - 1) : 32;
            if (fIncl < fInv) {
                int contrib = (tid <= fIncl) ? val : 0;
#pragma unroll
                for (int o = 16; o; o >>= 1) contrib += __shfl_xor_sync(0xffffffffu, contrib, o);
                run += contrib;
                break;
            } else {
                int contrib = (tid < fInv) ? val : 0;
#pragma unroll
                for (int o = 16; o; o >>= 1) contrib += __shfl_xor_sync(0xffffffffu, contrib, o);
                run += contrib;
                j -= fInv;
            }
        }
        if (tid == 0) {
            atomicExch(&g_desc[bid], (2ULL << 32) | (unsigned)(run + agg));
            s_run = run;
        }
    }
    __syncthreads();
    const int run = s_run;
    if (idx < NN) {
        int ex = run + s[tid] - v;
        g_rowptr[idx] = ex;
        g_wp[idx] = ex;
        g_dinv[idx] = rsqrtf((float)v + 1.0f);
        g_cnt[idx] = 0;
    }
    if (bid == NBLK_SCAN - 1 && tid == 511) g_rowptr[NN] = run + agg;
}

// ---------------- scatter ----------------
__global__ void scatter_kernel(const int* __restrict__ ei) {
    int e4 = blockIdx.x * blockDim.x + threadIdx.x;
    if (e4 < EE / 4) {
        int4 s = ((const int4*)ei)[e4];
        int4 d = ((const int4*)(ei + EE))[e4];
        g_col[atomicAdd(&g_wp[d.x], 1)] = s.x;
        g_col[atomicAdd(&g_wp[d.y], 1)] = s.y;
        g_col[atomicAdd(&g_wp[d.z], 1)] = s.z;
        g_col[atomicAdd(&g_wp[d.w], 1)] = s.w;
    }
}

// ---------------- fused MLP (no dinv dependency: writes raw h0) ----------------
__global__ __launch_bounds__(256, 2) void mlp_kernel(const float* __restrict__ x,
                                                     const float* __restrict__ w3,
                                                     const float* __restrict__ b3) {
    extern __shared__ char smem[];
    const uint32_t sb = smem_u32(smem);
    __nv_bfloat16* H1hi = (__nv_bfloat16*)(smem + OFF_H1HI);
    __nv_bfloat16* H1lo = (__nv_bfloat16*)(smem + OFF_H1LO);
    float* part = (float*)(smem + OFF_PART);
    float* b1s = (float*)(smem + OFF_B1);
    float* b2s = (float*)(smem + OFF_B2);
    float* w3s = (float*)(smem + OFF_W3);
    float* b3s = (float*)(smem + OFF_B3);

    const int tid = threadIdx.x;
    const int wid = tid >> 5, lane = tid & 31;
    const int wm = wid & 1, wn = wid >> 1;
    const int lq = lane >> 2, lr = lane & 3;
    const long rbase = (long)blockIdx.x * TM;

    const int alrow = tid >> 2;
    const int alcol = (tid & 3) * 8;
    const long grow_ld = rbase + alrow;
    const float4* xrow = (grow_ld < NN) ? (const float4*)(x + grow_ld * 512 + alcol) : (const float4*)0;
    const uint32_t a_st = (uint32_t)(alrow * SA + alcol);
    const int wlrow = tid >> 1;
    const int wlcol = (tid & 1) * 16;
    const uint32_t w_st = (uint32_t)(wlrow * SA + wlcol);

    if (tid < 128) { b1s[tid] = g_b1e[tid]; b2s[tid] = g_b2e[tid]; }
    if (tid < 3)   { b3s[tid] = b3[tid]; }
    if (tid >= 128 && tid < 224) ((float4*)w3s)[tid - 128] = ((const float4*)w3)[tid - 128];

    float acc[2][4][4];
#pragma unroll
    for (int mi = 0; mi < 2; mi++)
#pragma unroll
        for (int ni = 0; ni < 4; ni++)
#pragma unroll
            for (int q = 0; q < 4; q++) acc[mi][ni][q] = 0.f;

    auto issue_w1 = [&](int c, int b) {
        const int k0 = c * 32;
        cp16(sb + WHI_OFF(b) + w_st * 2,      &g_w1hi[wlrow * 512 + k0 + wlcol]);
        cp16(sb + WHI_OFF(b) + w_st * 2 + 16, &g_w1hi[wlrow * 512 + k0 + wlcol + 8]);
        cp16(sb + WLO_OFF(b) + w_st * 2,      &g_w1lo[wlrow * 512 + k0 + wlcol]);
        cp16(sb + WLO_OFF(b) + w_st * 2 + 16, &g_w1lo[wlrow * 512 + k0 + wlcol + 8]);
    };
    auto issue_w2 = [&](int c, int b) {
        const int k0 = c * 32;
        cp16(sb + WHI_OFF(b) + w_st * 2,      &g_w2hi[wlrow * 128 + k0 + wlcol]);
        cp16(sb + WHI_OFF(b) + w_st * 2 + 16, &g_w2hi[wlrow * 128 + k0 + wlcol + 8]);
        cp16(sb + WLO_OFF(b) + w_st * 2,      &g_w2lo[wlrow * 128 + k0 + wlcol]);
        cp16(sb + WLO_OFF(b) + w_st * 2 + 16, &g_w2lo[wlrow * 128 + k0 + wlcol + 8]);
    };
    float4 xr[2];
    auto ldg_x = [&](int c) {
        const int k04 = c * 8 + (tid & 3) * 2;
        if (xrow) { xr[0] = ((const float4*)(x + grow_ld * 512))[k04];
                    xr[1] = ((const float4*)(x + grow_ld * 512))[k04 + 1]; }
        else { xr[0] = xr[1] = make_float4(0.f, 0.f, 0.f, 0.f); }
    };
    auto sts_x = [&](int b) {
        char* hbase = smem + AHI_OFF(b);
        char* lbase = smem + ALO_OFF(b);
#pragma unroll
        for (int i = 0; i < 2; i++) {
            float4 v = xr[i];
            __nv_bfloat16 hx = __float2bfloat16(v.x), hy = __float2bfloat16(v.y);
            __nv_bfloat16 hz = __float2bfloat16(v.z), hw = __float2bfloat16(v.w);
            __nv_bfloat16 lx = __float2bfloat16(v.x - __bfloat162float(hx));
            __nv_bfloat16 ly = __float2bfloat16(v.y - __bfloat162float(hy));
            __nv_bfloat16 lz = __float2bfloat16(v.z - __bfloat162float(hz));
            __nv_bfloat16 lw = __float2bfloat16(v.w - __bfloat162float(hw));
            uint32_t eo = (a_st + i * 4) * 2;
            *(uint2*)(hbase + eo) = make_uint2(pk2(hx, hy), pk2(hz, hw));
            *(uint2*)(lbase + eo) = make_uint2(pk2(lx, ly), pk2(lz, lw));
        }
    };

    // ===== GEMM1 =====
    ldg_x(0);
    issue_w1(0, 0);
    CP_COMMIT();
    sts_x(0);
    CP_WAIT0();
    __syncthreads();

#pragma unroll 1
    for (int c = 0; c < 16; c++) {
        const int buf = c & 1, nbuf = buf ^ 1;
        if (c < 15) {
            issue_w1(c + 1, nbuf);
            CP_COMMIT();
            ldg_x(c + 1);
        }
        mma_chunk32(sb, AHI_OFF(buf), ALO_OFF(buf), SA, 0, WHI_OFF(buf), WLO_OFF(buf),
                    acc, wm, wn, lane);
        if (c < 15) { sts_x(nbuf); CP_WAIT0(); }
        __syncthreads();
    }

    issue_w2(0, 0); CP_COMMIT();
    issue_w2(1, 1); CP_COMMIT();

    // ===== epilogue 1 =====
#pragma unroll
    for (int mi = 0; mi < 2; mi++) {
        const int r = wm * 32 + mi * 16 + lq;
#pragma unroll
        for (int ni = 0; ni < 4; ni++) {
            const int c = wn * 32 + ni * 8 + lr * 2;
            float* a = acc[mi][ni];
            float bb0 = b1s[c], bb1 = b1s[c + 1];
            float v0 = fmaxf(a[0] + bb0, 0.f), v1 = fmaxf(a[1] + bb1, 0.f);
            float v2 = fmaxf(a[2] + bb0, 0.f), v3 = fmaxf(a[3] + bb1, 0.f);
            __nv_bfloat16 h0 = __float2bfloat16(v0), h1 = __float2bfloat16(v1);
            __nv_bfloat16 h2 = __float2bfloat16(v2), h3 = __float2bfloat16(v3);
            *(uint32_t*)&H1hi[r * SH + c] = pk2(h0, h1);
            *(uint32_t*)&H1lo[r * SH + c] =
                pk2(__float2bfloat16(v0 - __bfloat162float(h0)), __float2bfloat16(v1 - __bfloat162float(h1)));
            *(uint32_t*)&H1hi[(r + 8) * SH + c] = pk2(h2, h3);
            *(uint32_t*)&H1lo[(r + 8) * SH + c] =
                pk2(__float2bfloat16(v2 - __bfloat162float(h2)), __float2bfloat16(v3 - __bfloat162float(h3)));
            a[0] = a[1] = a[2] = a[3] = 0.f;
        }
    }

    // ===== GEMM2 =====
    CP_WAIT1(); __syncthreads();
    mma_chunk32(sb, OFF_H1HI, OFF_H1LO, SH, 0, WHI_OFF(0), WLO_OFF(0), acc, wm, wn, lane);
    __syncthreads();
    issue_w2(2, 0); CP_COMMIT();
    CP_WAIT1(); __syncthreads();
    mma_chunk32(sb, OFF_H1HI, OFF_H1LO, SH, 32, WHI_OFF(1), WLO_OFF(1), acc, wm, wn, lane);
    __syncthreads();
    issue_w2(3, 1); CP_COMMIT();
    CP_WAIT1(); __syncthreads();
    mma_chunk32(sb, OFF_H1HI, OFF_H1LO, SH, 64, WHI_OFF(0), WLO_OFF(0), acc, wm, wn, lane);
    CP_WAIT0(); __syncthreads();
    mma_chunk32(sb, OFF_H1HI, OFF_H1LO, SH, 96, WHI_OFF(1), WLO_OFF(1), acc, wm, wn, lane);

    // ===== epilogue 2 =====
    float o[2][2][3];
#pragma unroll
    for (int mi = 0; mi < 2; mi++)
#pragma unroll
        for (int hf = 0; hf < 2; hf++) o[mi][hf][0] = o[mi][hf][1] = o[mi][hf][2] = 0.f;
#pragma unroll
    for (int mi = 0; mi < 2; mi++) {
        const int r = wm * 32 + mi * 16 + lq;
#pragma unroll
        for (int ni = 0; ni < 4; ni++) {
            const int c = wn * 32 + ni * 8 + lr * 2;
            const float w30 = w3s[c], w31 = w3s[c + 1];
            const float w40 = w3s[128 + c], w41 = w3s[128 + c + 1];
            const float w50 = w3s[256 + c], w51 = w3s[256 + c + 1];
            const float bb0 = b2s[c], bb1 = b2s[c + 1];
            const float* a = acc[mi][ni];
            {
                uint32_t hh = *(const uint32_t*)&H1hi[r * SH + c];
                uint32_t hl = *(const uint32_t*)&H1lo[r * SH + c];
                float g0 = bflo(hh) + bflo(hl) + fmaxf(a[0] + bb0, 0.f);
                float g1 = bfhi(hh) + bfhi(hl) + fmaxf(a[1] + bb1, 0.f);
                o[mi][0][0] = fmaf(g0, w30, fmaf(g1, w31, o[mi][0][0]));
                o[mi][0][1] = fmaf(g0, w40, fmaf(g1, w41, o[mi][0][1]));
                o[mi][0][2] = fmaf(g0, w50, fmaf(g1, w51, o[mi][0][2]));
            }
            {
                uint32_t hh = *(const uint32_t*)&H1hi[(r + 8) * SH + c];
                uint32_t hl = *(const uint32_t*)&H1lo[(r + 8) * SH + c];
                float g0 = bflo(hh) + bflo(hl) + fmaxf(a[2] + bb0, 0.f);
                float g1 = bfhi(hh) + bfhi(hl) + fmaxf(a[3] + bb1, 0.f);
                o[mi][1][0] = fmaf(g0, w30, fmaf(g1, w31, o[mi][1][0]));
                o[mi][1][1] = fmaf(g0, w40, fmaf(g1, w41, o[mi][1][1]));
                o[mi][1][2] = fmaf(g0, w50, fmaf(g1, w51, o[mi][1][2]));
            }
        }
    }
#pragma unroll
    for (int mi = 0; mi < 2; mi++)
#pragma unroll
        for (int hf = 0; hf < 2; hf++)
#pragma unroll
            for (int j = 0; j < 3; j++) {
                o[mi][hf][j] += __shfl_xor_sync(0xffffffffu, o[mi][hf][j], 1);
                o[mi][hf][j] += __shfl_xor_sync(0xffffffffu, o[mi][hf][j], 2);
            }
    if (lr == 0) {
#pragma unroll
        for (int mi = 0; mi < 2; mi++)
#pragma unroll
            for (int hf = 0; hf < 2; hf++) {
                const int r = wm * 32 + mi * 16 + lq + hf * 8;
                float* p = &part[(wn * 64 + r) * 3];
                p[0] = o[mi][hf][0]; p[1] = o[mi][hf][1]; p[2] = o[mi][hf][2];
            }
    }
    __syncthreads();
    if (tid < 64) {
        const long grow = rbase + tid;
        if (grow < NN) {
            float s0 = b3s[0], s1 = b3s[1], s2 = b3s[2];
#pragma unroll
            for (int w = 0; w < 4; w++) {
                s0 += part[(w * 64 + tid) * 3 + 0];
                s1 += part[(w * 64 + tid) * 3 + 1];
                s2 += part[(w * 64 + tid) * 3 + 2];
            }
            g_h0a[grow] = make_float4(ALPHAF * s0, ALPHAF * s1, ALPHAF * s2, 0.f);
            g_yB[grow] = make_float4(s0, s1, s2, 0.f);  // raw h0
        }
    }
}

// ---------------- persistent fused: yA init + 10x propagation + log_softmax -------------
__global__ __launch_bounds__(256, 6) void fused_graph_kernel(float* __restrict__ out) {
    // phase 0: yA = dinv * h0raw (h0raw in yB)
    for (int i = blockIdx.x * blockDim.x + threadIdx.x; i < NN; i += FGRID * 256) {
        float dv = g_dinv[i];
        float4 z = g_yB[i];
        stcg4(&g_yA[i], make_float4(dv * z.x, dv * z.y, dv * z.z, 0.f));
    }
    gbar(1u);

    const int gwarp = (blockIdx.x * 256 + threadIdx.x) >> 5;
    const int lane = threadIdx.x & 31;
    const int nwarps = FGRID * 8;

#pragma unroll 1
    for (int it = 0; it < KITER; it++) {
        const float4* yin = (it & 1) ? g_yB : g_yA;
        float4* yout = (it & 1) ? g_yA : g_yB;
#pragma unroll 1
        for (int node = gwarp; node < NN; node += nwarps) {
            const int s0 = __ldg(&g_rowptr[node]), s1 = __ldg(&g_rowptr[node + 1]);
            float4 self = __ldg(&yin[node]);      // L1 ok: flushed at each gbar
            float4 h = __ldg(&g_h0a[node]);
            float dv = __ldg(&g_dinv[node]);
            float a0 = 0.f, a1 = 0.f, a2 = 0.f;
            for (int e = s0 + lane; e < s1; e += 32) {
                float4 v = __ldg(&yin[__ldg(&g_col[e])]);
                a0 += v.x; a1 += v.y; a2 += v.z;
            }
#pragma unroll
            for (int o = 16; o > 0; o >>= 1) {
                a0 += __shfl_xor_sync(0xffffffffu, a0, o);
                a1 += __shfl_xor_sync(0xffffffffu, a1, o);
                a2 += __shfl_xor_sync(0xffffffffu, a2, o);
            }
            if (lane == 0) {
                float c = (1.0f - ALPHAF) * dv;
                float z0 = c * (a0 + self.x) + h.x;
                float z1 = c * (a1 + self.y) + h.y;
                float z2 = c * (a2 + self.z) + h.z;
                if (it == KITER - 1) {
                    float m = fmaxf(z0, fmaxf(z1, z2));
                    float l = m + logf(expf(z0 - m) + expf(z1 - m) + expf(z2 - m));
                    out[3 * node + 0] = z0 - l;
                    out[3 * node + 1] = z1 - l;
                    out[3 * node + 2] = z2 - l;
                } else {
                    stcg4(&yout[node], make_float4(dv * z0, dv * z1, dv * z2, 0.f));
                }
            }
        }
        if (it < KITER - 1) gbar((unsigned)(it & 1));  // 10 total flips incl. init: even
    }
}

extern "C" void kernel_launch(void* const* d_in, const int* in_sizes, int n_in,
                              void* d_out, int out_size) {
    const float* x  = (const float*)d_in[0];
    const int* ei   = (const int*)d_in[1];
    const float* w1 = (const float*)d_in[2];
    const float* b1 = (const float*)d_in[3];
    const float* g1 = (const float*)d_in[4];
    const float* be1 = (const float*)d_in[5];
    const float* m1 = (const float*)d_in[6];
    const float* v1 = (const float*)d_in[7];
    const float* w2 = (const float*)d_in[8];
    const float* b2 = (const float*)d_in[9];
    const float* g2 = (const float*)d_in[10];
    const float* be2 = (const float*)d_in[11];
    const float* m2 = (const float*)d_in[12];
    const float* v2 = (const float*)d_in[13];
    const float* w3 = (const float*)d_in[14];
    const float* b3 = (const float*)d_in[15];
    float* out = (float*)d_out;

    cudaFuncSetAttribute(mlp_kernel, cudaFuncAttributeMaxDynamicSharedMemorySize, SMEM_MLP);

    // Fork a side stream inside graph capture (event-ordered; created fresh each call,
    // never destroyed during capture; no device memory allocated).
    cudaStream_t s1;
    cudaEvent_t evF, evM;
    cudaStreamCreateWithFlags(&s1, cudaStreamNonBlocking);
    cudaEventCreateWithFlags(&evF, cudaEventDisableTiming);
    cudaEventCreateWithFlags(&evM, cudaEventDisableTiming);

    cudaEventRecord(evF, 0);
    cudaStreamWaitEvent(s1, evF, 0);

    // NULL stream: CSR chain;  s1: weights + MLP (independent until fused)
    hist_kernel<<<(EE / 4 + 255) / 256, 256>>>(ei);                          // k1 (NULL)
    prepw_kernel<<<128, 128, 0, s1>>>(w1, b1, g1, be1, m1, v1,
                                      w2, b2, g2, be2, m2, v2);              // k2 (s1)
    scan_kernel<<<NBLK_SCAN, 512>>>();                                       // k3 (NULL)
    mlp_kernel<<<NTILES, 256, SMEM_MLP, s1>>>(x, w3, b3);                    // k4 (s1) <- profiled
    scatter_kernel<<<(EE / 4 + 255) / 256, 256>>>(ei);                       // k5 (NULL)
    cudaEventRecord(evM, s1);
    cudaStreamWaitEvent(0, evM, 0);
    fused_graph_kernel<<<FGRID, 256>>>(out);                                 // k6 (NULL)
}

// round 11
// speedup vs baseline: 1.1938x; 1.1938x over previous
#include <cuda_runtime.h>
#include <cuda_bf16.h>
#include <math.h>
#include <stdint.h>

#define NN 100000
#define EE 3200000
#define KITER 10
#define ALPHAF 0.1f
#define EPSB 1e-5f
#define NBLK_SCAN 196
#define TM 64
#define NTILES ((NN + TM - 1) / TM)
#define FGRID 888   // 148 SMs x 6 CTAs co-resident
#define LPG 8       // lanes per node-group in propagation

// ---- smem layout (bytes) ----
#define SA 40
#define SH 136
#define A_CHUNK_B (64 * SA * 2)
#define W_CHUNK_B (128 * SA * 2)
#define OFF_A    0
#define OFF_W    (OFF_A + 4 * A_CHUNK_B)
#define OFF_H1HI (OFF_W + 4 * W_CHUNK_B)
#define OFF_H1LO (OFF_H1HI + 64 * SH * 2)
#define OFF_PART (OFF_H1LO + 64 * SH * 2)
#define OFF_B1   (OFF_PART + 3072)
#define OFF_B2   (OFF_B1 + 512)
#define OFF_W3   (OFF_B2 + 512)
#define OFF_B3   (OFF_W3 + 1536)
#define SMEM_MLP (OFF_B3 + 16)

#define AHI_OFF(b) (OFF_A + (b) * A_CHUNK_B)
#define ALO_OFF(b) (OFF_A + 2 * A_CHUNK_B + (b) * A_CHUNK_B)
#define WHI_OFF(b) (OFF_W + (b) * W_CHUNK_B)
#define WLO_OFF(b) (OFF_W + 2 * W_CHUNK_B + (b) * W_CHUNK_B)

// ---------------- device scratch ----------------
__device__ __nv_bfloat16 g_w1hi[128 * 512], g_w1lo[128 * 512];
__device__ __nv_bfloat16 g_w2hi[128 * 128], g_w2lo[128 * 128];
__device__ float g_b1e[128], g_b2e[128];
__device__ float4 g_h0a[NN];   // alpha * h0
__device__ float4 g_yA[NN];    // y ping (init: dinv*h0, written by mlp)
__device__ float4 g_yB[NN];    // y pong
__device__ float g_dinv[NN];
__device__ int g_cnt[NN];
__device__ int g_rowptr[NN + 1];
__device__ int g_wp[NN];
__device__ int g_col[EE];
__device__ unsigned long long g_desc[NBLK_SCAN];
__device__ volatile unsigned g_count0;
__device__ volatile unsigned g_sense0;

// ---------------- helpers ----------------
__device__ __forceinline__ uint32_t smem_u32(const void* p) {
    uint32_t a;
    asm("{ .reg .u64 t; cvta.to.shared.u64 t, %1; cvt.u32.u64 %0, t; }" : "=r"(a) : "l"(p));
    return a;
}
__device__ __forceinline__ uint16_t bfbits(__nv_bfloat16 h) { __nv_bfloat16_raw r = h; return r.x; }
__device__ __forceinline__ uint32_t pk2(__nv_bfloat16 a, __nv_bfloat16 b) {
    return (uint32_t)bfbits(a) | ((uint32_t)bfbits(b) << 16);
}
__device__ __forceinline__ float bflo(uint32_t u) { return __uint_as_float(u << 16); }
__device__ __forceinline__ float bfhi(uint32_t u) { return __uint_as_float(u & 0xFFFF0000u); }

__device__ __forceinline__ void cp16(uint32_t dst, const void* src) {
    asm volatile("cp.async.cg.shared.global [%0], [%1], 16;" :: "r"(dst), "l"(src));
}
#define CP_COMMIT() asm volatile("cp.async.commit_group;" ::: "memory")
#define CP_WAIT0()  asm volatile("cp.async.wait_group 0;" ::: "memory")
#define CP_WAIT1()  asm volatile("cp.async.wait_group 1;" ::: "memory")

__device__ __forceinline__ void ldsm4(uint32_t r[4], uint32_t a) {
    asm volatile("ldmatrix.sync.aligned.m8n8.x4.shared.b16 {%0,%1,%2,%3}, [%4];"
        : "=r"(r[0]), "=r"(r[1]), "=r"(r[2]), "=r"(r[3]) : "r"(a));
}
__device__ __forceinline__ void mma16816(float c[4], const uint32_t a[4], uint32_t b0, uint32_t b1) {
    asm volatile("mma.sync.aligned.m16n8k16.row.col.f32.bf16.bf16.f32 "
        "{%0,%1,%2,%3}, {%4,%5,%6,%7}, {%8,%9}, {%0,%1,%2,%3};"
        : "+f"(c[0]), "+f"(c[1]), "+f"(c[2]), "+f"(c[3])
        : "r"(a[0]), "r"(a[1]), "r"(a[2]), "r"(a[3]), "r"(b0), "r"(b1));
}

__device__ __forceinline__ float4 ldcg4(const float4* p) {
    float4 v;
    asm volatile("ld.global.cg.v4.f32 {%0,%1,%2,%3}, [%4];"
        : "=f"(v.x), "=f"(v.y), "=f"(v.z), "=f"(v.w) : "l"(p));
    return v;
}
__device__ __forceinline__ void stcg4(float4* p, float4 v) {
    asm volatile("st.global.cg.v4.f32 [%0], {%1,%2,%3,%4};"
        :: "l"(p), "f"(v.x), "f"(v.y), "f"(v.z), "f"(v.w));
}

// sense-reversing grid barrier; even total flips per launch -> self-resetting for replay
__device__ __forceinline__ void gbar(unsigned s) {
    __syncthreads();
    __threadfence();
    if (threadIdx.x == 0) {
        if (atomicAdd((unsigned*)&g_count0, 1u) == FGRID - 1) {
            g_count0 = 0;
            __threadfence();
            g_sense0 = s;
        } else {
            while (g_sense0 != s) { }
        }
    }
    __syncthreads();
}

// one K=32 chunk of split-2 MMA, warp tile M32 x N32
__device__ __forceinline__ void mma_chunk32(uint32_t sb, int a_hi_off, int a_lo_off, int a_stride,
                                            int a_kcol, int w_hi_off, int w_lo_off,
                                            float acc[2][4][4], int wm, int wn, int lane) {
    const int arow = (lane & 15);
    const int asel = (lane >> 4) & 1;
    const int seg = lane >> 3;
    const int b_nrow = (seg >> 1) * 8 + (lane & 7);
    const int b_kofs = (seg & 1) * 8;
#pragma unroll
    for (int ks = 0; ks < 2; ks++) {
        const int k0a = a_kcol + ks * 16;
        const int k0w = ks * 16;
        uint32_t ah[2][4], al[2][4];
#pragma unroll
        for (int mi = 0; mi < 2; mi++) {
            const int row = wm * 32 + mi * 16 + arow;
            ldsm4(ah[mi], sb + a_hi_off + (row * a_stride + k0a + asel * 8) * 2);
            ldsm4(al[mi], sb + a_lo_off + (row * a_stride + k0a + asel * 8) * 2);
        }
#pragma unroll
        for (int ni2 = 0; ni2 < 2; ni2++) {
            const int nrow = wn * 32 + ni2 * 16 + b_nrow;
            uint32_t bh[4], bl[4];
            ldsm4(bh, sb + w_hi_off + (nrow * SA + k0w + b_kofs) * 2);
            ldsm4(bl, sb + w_lo_off + (nrow * SA + k0w + b_kofs) * 2);
#pragma unroll
            for (int h = 0; h < 2; h++) {
                const int ni = ni2 * 2 + h;
#pragma unroll
                for (int mi = 0; mi < 2; mi++) {
                    mma16816(acc[mi][ni], ah[mi], bh[2 * h], bh[2 * h + 1]);
                    mma16816(acc[mi][ni], ah[mi], bl[2 * h], bl[2 * h + 1]);
                    mma16816(acc[mi][ni], al[mi], bh[2 * h], bh[2 * h + 1]);
                }
            }
        }
    }
}

// ---------------- merged prep + hist (+ desc clear) ----------------
__global__ void histprep_kernel(const int* __restrict__ ei,
                                const float* __restrict__ w1, const float* __restrict__ b1,
                                const float* __restrict__ g1, const float* __restrict__ be1,
                                const float* __restrict__ m1, const float* __restrict__ v1,
                                const float* __restrict__ w2, const float* __restrict__ b2,
                                const float* __restrict__ g2, const float* __restrict__ be2,
                                const float* __restrict__ m2, const float* __restrict__ v2) {
    if (blockIdx.x < 128) {
        const int j = blockIdx.x;
        const float s1 = g1[j] * rsqrtf(v1[j] + EPSB);
        const float s2 = g2[j] * rsqrtf(v2[j] + EPSB);
        for (int k = threadIdx.x; k < 512; k += blockDim.x) {
            float w = s1 * w1[j * 512 + k];
            __nv_bfloat16 h = __float2bfloat16(w);
            g_w1hi[j * 512 + k] = h;
            g_w1lo[j * 512 + k] = __float2bfloat16(w - __bfloat162float(h));
        }
        for (int k = threadIdx.x; k < 128; k += blockDim.x) {
            float w = s2 * w2[j * 128 + k];
            __nv_bfloat16 h = __float2bfloat16(w);
            g_w2hi[j * 128 + k] = h;
            g_w2lo[j * 128 + k] = __float2bfloat16(w - __bfloat162float(h));
        }
        if (threadIdx.x == 0) {
            g_b1e[j] = s1 * (b1[j] - m1[j]) + be1[j];
            g_b2e[j] = s2 * (b2[j] - m2[j]) + be2[j];
        }
    } else {
        const int gt = (blockIdx.x - 128) * blockDim.x + threadIdx.x;
        if (gt < NBLK_SCAN) g_desc[gt] = 0ULL;
        if (gt < EE / 4) {
            int4 d = ((const int4*)(ei + EE))[gt];
            atomicAdd(&g_cnt[d.x], 1);
            atomicAdd(&g_cnt[d.y], 1);
            atomicAdd(&g_cnt[d.z], 1);
            atomicAdd(&g_cnt[d.w], 1);
        }
    }
}

// ---------------- decoupled-lookback scan (+ cnt re-zero) ----------------
__global__ __launch_bounds__(512) void scan_kernel() {
    __shared__ int s[512];
    __shared__ int s_run;
    const int tid = threadIdx.x, bid = blockIdx.x;
    const int idx = bid * 512 + tid;
    const int v = (idx < NN) ? g_cnt[idx] : 0;
    s[tid] = v;
    __syncthreads();
    for (int off = 1; off < 512; off <<= 1) {
        int t = (tid >= off) ? s[tid - off] : 0;
        __syncthreads();
        s[tid] += t;
        __syncthreads();
    }
    const int agg = s[511];
    if (tid == 0) {
        unsigned long long d = (bid == 0) ? ((2ULL << 32) | (unsigned)agg)
                                          : ((1ULL << 32) | (unsigned)agg);
        atomicExch(&g_desc[bid], d);
        if (bid == 0) s_run = 0;
    }
    if (bid > 0 && tid < 32) {
        int run = 0;
        int j = bid - 1;
        while (true) {
            int ridx = j - tid;
            unsigned long long d = (ridx >= 0) ? atomicAdd(&g_desc[ridx], 0ULL) : (2ULL << 32);
            int st = (int)(d >> 32);
            int val = (int)(d & 0xffffffffu);
            unsigned inv  = __ballot_sync(0xffffffffu, st == 0);
            unsigned incl = __ballot_sync(0xffffffffu, st == 2);
            int fInv  = inv  ? (__ffs(inv) - 1)  : 32;
            int fIncl = incl ? (__ffs(incl) - 1) : 32;
            if (fIncl < fInv) {
                int contrib = (tid <= fIncl) ? val : 0;
#pragma unroll
                for (int o = 16; o; o >>= 1) contrib += __shfl_xor_sync(0xffffffffu, contrib, o);
                run += contrib;
                break;
            } else {
                int contrib = (tid < fInv) ? val : 0;
#pragma unroll
                for (int o = 16; o; o >>= 1) contrib += __shfl_xor_sync(0xffffffffu, contrib, o);
                run += contrib;
                j -= fInv;
            }
        }
        if (tid == 0) {
            atomicExch(&g_desc[bid], (2ULL << 32) | (unsigned)(run + agg));
            s_run = run;
        }
    }
    __syncthreads();
    const int run = s_run;
    if (idx < NN) {
        int ex = run + s[tid] - v;
        g_rowptr[idx] = ex;
        g_wp[idx] = ex;
        g_dinv[idx] = rsqrtf((float)v + 1.0f);
        g_cnt[idx] = 0;
    }
    if (bid == NBLK_SCAN - 1 && tid == 511) g_rowptr[NN] = run + agg;
}

// ---------------- fused MLP (writes h0a and yA = dinv*h0; needs scan first) -------------
__global__ __launch_bounds__(256, 2) void mlp_kernel(const float* __restrict__ x,
                                                     const float* __restrict__ w3,
                                                     const float* __restrict__ b3) {
    extern __shared__ char smem[];
    const uint32_t sb = smem_u32(smem);
    __nv_bfloat16* H1hi = (__nv_bfloat16*)(smem + OFF_H1HI);
    __nv_bfloat16* H1lo = (__nv_bfloat16*)(smem + OFF_H1LO);
    float* part = (float*)(smem + OFF_PART);
    float* b1s = (float*)(smem + OFF_B1);
    float* b2s = (float*)(smem + OFF_B2);
    float* w3s = (float*)(smem + OFF_W3);
    float* b3s = (float*)(smem + OFF_B3);

    const int tid = threadIdx.x;
    const int wid = tid >> 5, lane = tid & 31;
    const int wm = wid & 1, wn = wid >> 1;
    const int lq = lane >> 2, lr = lane & 3;
    const long rbase = (long)blockIdx.x * TM;

    const int alrow = tid >> 2;
    const int alcol = (tid & 3) * 8;
    const long grow_ld = rbase + alrow;
    const float4* xrow = (grow_ld < NN) ? (const float4*)(x + grow_ld * 512 + alcol) : (const float4*)0;
    const uint32_t a_st = (uint32_t)(alrow * SA + alcol);
    const int wlrow = tid >> 1;
    const int wlcol = (tid & 1) * 16;
    const uint32_t w_st = (uint32_t)(wlrow * SA + wlcol);

    if (tid < 128) { b1s[tid] = g_b1e[tid]; b2s[tid] = g_b2e[tid]; }
    if (tid < 3)   { b3s[tid] = b3[tid]; }
    if (tid >= 128 && tid < 224) ((float4*)w3s)[tid - 128] = ((const float4*)w3)[tid - 128];

    float acc[2][4][4];
#pragma unroll
    for (int mi = 0; mi < 2; mi++)
#pragma unroll
        for (int ni = 0; ni < 4; ni++)
#pragma unroll
            for (int q = 0; q < 4; q++) acc[mi][ni][q] = 0.f;

    auto issue_w1 = [&](int c, int b) {
        const int k0 = c * 32;
        cp16(sb + WHI_OFF(b) + w_st * 2,      &g_w1hi[wlrow * 512 + k0 + wlcol]);
        cp16(sb + WHI_OFF(b) + w_st * 2 + 16, &g_w1hi[wlrow * 512 + k0 + wlcol + 8]);
        cp16(sb + WLO_OFF(b) + w_st * 2,      &g_w1lo[wlrow * 512 + k0 + wlcol]);
        cp16(sb + WLO_OFF(b) + w_st * 2 + 16, &g_w1lo[wlrow * 512 + k0 + wlcol + 8]);
    };
    auto issue_w2 = [&](int c, int b) {
        const int k0 = c * 32;
        cp16(sb + WHI_OFF(b) + w_st * 2,      &g_w2hi[wlrow * 128 + k0 + wlcol]);
        cp16(sb + WHI_OFF(b) + w_st * 2 + 16, &g_w2hi[wlrow * 128 + k0 + wlcol + 8]);
        cp16(sb + WLO_OFF(b) + w_st * 2,      &g_w2lo[wlrow * 128 + k0 + wlcol]);
        cp16(sb + WLO_OFF(b) + w_st * 2 + 16, &g_w2lo[wlrow * 128 + k0 + wlcol + 8]);
    };
    float4 xr[2];
    auto ldg_x = [&](int c) {
        const int k04 = c * 8 + (tid & 3) * 2;
        if (xrow) { xr[0] = ((const float4*)(x + grow_ld * 512))[k04];
                    xr[1] = ((const float4*)(x + grow_ld * 512))[k04 + 1]; }
        else { xr[0] = xr[1] = make_float4(0.f, 0.f, 0.f, 0.f); }
    };
    auto sts_x = [&](int b) {
        char* hbase = smem + AHI_OFF(b);
        char* lbase = smem + ALO_OFF(b);
#pragma unroll
        for (int i = 0; i < 2; i++) {
            float4 v = xr[i];
            __nv_bfloat16 hx = __float2bfloat16(v.x), hy = __float2bfloat16(v.y);
            __nv_bfloat16 hz = __float2bfloat16(v.z), hw = __float2bfloat16(v.w);
            __nv_bfloat16 lx = __float2bfloat16(v.x - __bfloat162float(hx));
            __nv_bfloat16 ly = __float2bfloat16(v.y - __bfloat162float(hy));
            __nv_bfloat16 lz = __float2bfloat16(v.z - __bfloat162float(hz));
            __nv_bfloat16 lw = __float2bfloat16(v.w - __bfloat162float(hw));
            uint32_t eo = (a_st + i * 4) * 2;
            *(uint2*)(hbase + eo) = make_uint2(pk2(hx, hy), pk2(hz, hw));
            *(uint2*)(lbase + eo) = make_uint2(pk2(lx, ly), pk2(lz, lw));
        }
    };

    // ===== GEMM1 =====
    ldg_x(0);
    issue_w1(0, 0);
    CP_COMMIT();
    sts_x(0);
    CP_WAIT0();
    __syncthreads();

#pragma unroll 1
    for (int c = 0; c < 16; c++) {
        const int buf = c & 1, nbuf = buf ^ 1;
        if (c < 15) {
            issue_w1(c + 1, nbuf);
            CP_COMMIT();
            ldg_x(c + 1);
        }
        mma_chunk32(sb, AHI_OFF(buf), ALO_OFF(buf), SA, 0, WHI_OFF(buf), WLO_OFF(buf),
                    acc, wm, wn, lane);
        if (c < 15) { sts_x(nbuf); CP_WAIT0(); }
        __syncthreads();
    }

    issue_w2(0, 0); CP_COMMIT();
    issue_w2(1, 1); CP_COMMIT();

    // ===== epilogue 1 =====
#pragma unroll
    for (int mi = 0; mi < 2; mi++) {
        const int r = wm * 32 + mi * 16 + lq;
#pragma unroll
        for (int ni = 0; ni < 4; ni++) {
            const int c = wn * 32 + ni * 8 + lr * 2;
            float* a = acc[mi][ni];
            float bb0 = b1s[c], bb1 = b1s[c + 1];
            float v0 = fmaxf(a[0] + bb0, 0.f), v1 = fmaxf(a[1] + bb1, 0.f);
            float v2 = fmaxf(a[2] + bb0, 0.f), v3 = fmaxf(a[3] + bb1, 0.f);
            __nv_bfloat16 h0 = __float2bfloat16(v0), h1 = __float2bfloat16(v1);
            __nv_bfloat16 h2 = __float2bfloat16(v2), h3 = __float2bfloat16(v3);
            *(uint32_t*)&H1hi[r * SH + c] = pk2(h0, h1);
            *(uint32_t*)&H1lo[r * SH + c] =
                pk2(__float2bfloat16(v0 - __bfloat162float(h0)), __float2bfloat16(v1 - __bfloat162float(h1)));
            *(uint32_t*)&H1hi[(r + 8) * SH + c] = pk2(h2, h3);
            *(uint32_t*)&H1lo[(r + 8) * SH + c] =
                pk2(__float2bfloat16(v2 - __bfloat162float(h2)), __float2bfloat16(v3 - __bfloat162float(h3)));
            a[0] = a[1] = a[2] = a[3] = 0.f;
        }
    }

    // ===== GEMM2 =====
    CP_WAIT1(); __syncthreads();
    mma_chunk32(sb, OFF_H1HI, OFF_H1LO, SH, 0, WHI_OFF(0), WLO_OFF(0), acc, wm, wn, lane);
    __syncthreads();
    issue_w2(2, 0); CP_COMMIT();
    CP_WAIT1(); __syncthreads();
    mma_chunk32(sb, OFF_H1HI, OFF_H1LO, SH, 32, WHI_OFF(1), WLO_OFF(1), acc, wm, wn, lane);
    __syncthreads();
    issue_w2(3, 1); CP_COMMIT();
    CP_WAIT1(); __syncthreads();
    mma_chunk32(sb, OFF_H1HI, OFF_H1LO, SH, 64, WHI_OFF(0), WLO_OFF(0), acc, wm, wn, lane);
    CP_WAIT0(); __syncthreads();
    mma_chunk32(sb, OFF_H1HI, OFF_H1LO, SH, 96, WHI_OFF(1), WLO_OFF(1), acc, wm, wn, lane);

    // ===== epilogue 2 =====
    float o[2][2][3];
#pragma unroll
    for (int mi = 0; mi < 2; mi++)
#pragma unroll
        for (int hf = 0; hf < 2; hf++) o[mi][hf][0] = o[mi][hf][1] = o[mi][hf][2] = 0.f;
#pragma unroll
    for (int mi = 0; mi < 2; mi++) {
        const int r = wm * 32 + mi * 16 + lq;
#pragma unroll
        for (int ni = 0; ni < 4; ni++) {
            const int c = wn * 32 + ni * 8 + lr * 2;
            const float w30 = w3s[c], w31 = w3s[c + 1];
            const float w40 = w3s[128 + c], w41 = w3s[128 + c + 1];
            const float w50 = w3s[256 + c], w51 = w3s[256 + c + 1];
            const float bb0 = b2s[c], bb1 = b2s[c + 1];
            const float* a = acc[mi][ni];
            {
                uint32_t hh = *(const uint32_t*)&H1hi[r * SH + c];
                uint32_t hl = *(const uint32_t*)&H1lo[r * SH + c];
                float g0 = bflo(hh) + bflo(hl) + fmaxf(a[0] + bb0, 0.f);
                float g1 = bfhi(hh) + bfhi(hl) + fmaxf(a[1] + bb1, 0.f);
                o[mi][0][0] = fmaf(g0, w30, fmaf(g1, w31, o[mi][0][0]));
                o[mi][0][1] = fmaf(g0, w40, fmaf(g1, w41, o[mi][0][1]));
                o[mi][0][2] = fmaf(g0, w50, fmaf(g1, w51, o[mi][0][2]));
            }
            {
                uint32_t hh = *(const uint32_t*)&H1hi[(r + 8) * SH + c];
                uint32_t hl = *(const uint32_t*)&H1lo[(r + 8) * SH + c];
                float g0 = bflo(hh) + bflo(hl) + fmaxf(a[2] + bb0, 0.f);
                float g1 = bfhi(hh) + bfhi(hl) + fmaxf(a[3] + bb1, 0.f);
                o[mi][1][0] = fmaf(g0, w30, fmaf(g1, w31, o[mi][1][0]));
                o[mi][1][1] = fmaf(g0, w40, fmaf(g1, w41, o[mi][1][1]));
                o[mi][1][2] = fmaf(g0, w50, fmaf(g1, w51, o[mi][1][2]));
            }
        }
    }
#pragma unroll
    for (int mi = 0; mi < 2; mi++)
#pragma unroll
        for (int hf = 0; hf < 2; hf++)
#pragma unroll
            for (int j = 0; j < 3; j++) {
                o[mi][hf][j] += __shfl_xor_sync(0xffffffffu, o[mi][hf][j], 1);
                o[mi][hf][j] += __shfl_xor_sync(0xffffffffu, o[mi][hf][j], 2);
            }
    if (lr == 0) {
#pragma unroll
        for (int mi = 0; mi < 2; mi++)
#pragma unroll
            for (int hf = 0; hf < 2; hf++) {
                const int r = wm * 32 + mi * 16 + lq + hf * 8;
                float* p = &part[(wn * 64 + r) * 3];
                p[0] = o[mi][hf][0]; p[1] = o[mi][hf][1]; p[2] = o[mi][hf][2];
            }
    }
    __syncthreads();
    if (tid < 64) {
        const long grow = rbase + tid;
        if (grow < NN) {
            float s0 = b3s[0], s1 = b3s[1], s2 = b3s[2];
#pragma unroll
            for (int w = 0; w < 4; w++) {
                s0 += part[(w * 64 + tid) * 3 + 0];
                s1 += part[(w * 64 + tid) * 3 + 1];
                s2 += part[(w * 64 + tid) * 3 + 2];
            }
            float dv = g_dinv[grow];   // scan ran before mlp
            g_h0a[grow] = make_float4(ALPHAF * s0, ALPHAF * s1, ALPHAF * s2, 0.f);
            g_yA[grow] = make_float4(dv * s0, dv * s1, dv * s2, 0.f);
        }
    }
}

// ---------------- persistent fused: scatter + 10x propagation + log_softmax -------------
// Propagation uses 8-lane node groups: 4 nodes/warp, 3-level reductions.
__global__ __launch_bounds__(256, 6) void fused_graph_kernel(const int* __restrict__ ei,
                                                             float* __restrict__ out) {
    // phase 0: CSR scatter
    for (int e4 = blockIdx.x * blockDim.x + threadIdx.x; e4 < EE / 4; e4 += FGRID * 256) {
        int4 s = ((const int4*)ei)[e4];
        int4 d = ((const int4*)(ei + EE))[e4];
        g_col[atomicAdd(&g_wp[d.x], 1)] = s.x;
        g_col[atomicAdd(&g_wp[d.y], 1)] = s.y;
        g_col[atomicAdd(&g_wp[d.z], 1)] = s.z;
        g_col[atomicAdd(&g_wp[d.w], 1)] = s.w;
    }
    gbar(1u);

    const int ggroup = (blockIdx.x * 256 + threadIdx.x) / LPG;
    const int gl = threadIdx.x & (LPG - 1);
    const int ngroups = FGRID * 256 / LPG;

#pragma unroll 1
    for (int it = 0; it < KITER; it++) {
        const float4* yin = (it & 1) ? g_yB : g_yA;
        float4* yout = (it & 1) ? g_yA : g_yB;
#pragma unroll 1
        for (int node = ggroup; node < NN; node += ngroups) {
            const int s0 = __ldg(&g_rowptr[node]), s1 = __ldg(&g_rowptr[node + 1]);
            float4 self = ldcg4(&yin[node]);
            float4 h = __ldg(&g_h0a[node]);
            float dv = __ldg(&g_dinv[node]);
            float a0 = 0.f, a1 = 0.f, a2 = 0.f;
            for (int e = s0 + gl; e < s1; e += LPG) {
                float4 v = ldcg4(&yin[__ldg(&g_col[e])]);
                a0 += v.x; a1 += v.y; a2 += v.z;
            }
#pragma unroll
            for (int o = LPG / 2; o > 0; o >>= 1) {
                a0 += __shfl_xor_sync(0xffffffffu, a0, o);
                a1 += __shfl_xor_sync(0xffffffffu, a1, o);
                a2 += __shfl_xor_sync(0xffffffffu, a2, o);
            }
            if (gl == 0) {
                float c = (1.0f - ALPHAF) * dv;
                float z0 = c * (a0 + self.x) + h.x;
                float z1 = c * (a1 + self.y) + h.y;
                float z2 = c * (a2 + self.z) + h.z;
                if (it == KITER - 1) {
                    float m = fmaxf(z0, fmaxf(z1, z2));
                    float l = m + logf(expf(z0 - m) + expf(z1 - m) + expf(z2 - m));
                    out[3 * node + 0] = z0 - l;
                    out[3 * node + 1] = z1 - l;
                    out[3 * node + 2] = z2 - l;
                } else {
                    stcg4(&yout[node], make_float4(dv * z0, dv * z1, dv * z2, 0.f));
                }
            }
        }
        if (it < KITER - 1) gbar((unsigned)(it & 1));  // 9 + 1 (scatter) = 10 flips: even
    }
}

extern "C" void kernel_launch(void* const* d_in, const int* in_sizes, int n_in,
                              void* d_out, int out_size) {
    const float* x  = (const float*)d_in[0];
    const int* ei   = (const int*)d_in[1];
    const float* w1 = (const float*)d_in[2];
    const float* b1 = (const float*)d_in[3];
    const float* g1 = (const float*)d_in[4];
    const float* be1 = (const float*)d_in[5];
    const float* m1 = (const float*)d_in[6];
    const float* v1 = (const float*)d_in[7];
    const float* w2 = (const float*)d_in[8];
    const float* b2 = (const float*)d_in[9];
    const float* g2 = (const float*)d_in[10];
    const float* be2 = (const float*)d_in[11];
    const float* m2 = (const float*)d_in[12];
    const float* v2 = (const float*)d_in[13];
    const float* w3 = (const float*)d_in[14];
    const float* b3 = (const float*)d_in[15];
    float* out = (float*)d_out;

    cudaFuncSetAttribute(mlp_kernel, cudaFuncAttributeMaxDynamicSharedMemorySize, SMEM_MLP);

    // 4 kernels, single stream; fused_graph_kernel is the 4th (profiled slot)
    histprep_kernel<<<128 + (EE / 4 + 255) / 256, 256>>>(ei,
        w1, b1, g1, be1, m1, v1, w2, b2, g2, be2, m2, v2);               // 1 (prep+hist+desc)
    scan_kernel<<<NBLK_SCAN, 512>>>();                                   // 2 (rowptr/wp/dinv, cnt=0)
    mlp_kernel<<<NTILES, 256, SMEM_MLP>>>(x, w3, b3);                    // 3 (h0a, yA=dinv*h0)
    fused_graph_kernel<<<FGRID, 256>>>(ei, out);                         // 4 <- profiled
}

// round 12
// speedup vs baseline: 1.1967x; 1.0024x over previous
#include <cuda_runtime.h>
#include <cuda_bf16.h>
#include <math.h>
#include <stdint.h>

#define NN 100000
#define EE 3200000
#define KITER 10
#define ALPHAF 0.1f
#define EPSB 1e-5f
#define NBLK_SCAN 196
#define TM 64
#define NTILES ((NN + TM - 1) / TM)
#define FGRID 888   // 148 SMs x 6 CTAs co-resident
#define LPG 8       // lanes per node-group in propagation

// ---- smem layout (bytes) ----
#define SA 40
#define SH 136
#define A_CHUNK_B (64 * SA * 2)
#define W_CHUNK_B (128 * SA * 2)
#define OFF_A    0
#define OFF_W    (OFF_A + 4 * A_CHUNK_B)
#define OFF_H1HI (OFF_W + 4 * W_CHUNK_B)
#define OFF_H1LO (OFF_H1HI + 64 * SH * 2)
#define OFF_PART (OFF_H1LO + 64 * SH * 2)
#define OFF_B1   (OFF_PART + 3072)
#define OFF_B2   (OFF_B1 + 512)
#define OFF_W3   (OFF_B2 + 512)
#define OFF_B3   (OFF_W3 + 1536)
#define SMEM_MLP (OFF_B3 + 16)

#define AHI_OFF(b) (OFF_A + (b) * A_CHUNK_B)
#define ALO_OFF(b) (OFF_A + 2 * A_CHUNK_B + (b) * A_CHUNK_B)
#define WHI_OFF(b) (OFF_W + (b) * W_CHUNK_B)
#define WLO_OFF(b) (OFF_W + 2 * W_CHUNK_B + (b) * W_CHUNK_B)

// ---------------- device scratch ----------------
__device__ __nv_bfloat16 g_w1hi[128 * 512], g_w1lo[128 * 512];
__device__ __nv_bfloat16 g_w2hi[128 * 128], g_w2lo[128 * 128];
__device__ float g_b1e[128], g_b2e[128];
__device__ float4 g_h0a[NN];   // alpha * h0
__device__ float4 g_yA[NN];    // y ping (init: dinv*h0, written by mlp)
__device__ float4 g_yB[NN];    // y pong
__device__ float g_dinv[NN];
__device__ int g_cnt[NN];
__device__ int g_rowptr[NN + 1];
__device__ int g_wp[NN];
__device__ int g_col[EE];
__device__ unsigned long long g_desc[NBLK_SCAN];
__device__ volatile unsigned g_count0;
__device__ volatile unsigned g_sense0;

// ---------------- helpers ----------------
__device__ __forceinline__ uint32_t smem_u32(const void* p) {
    uint32_t a;
    asm("{ .reg .u64 t; cvta.to.shared.u64 t, %1; cvt.u32.u64 %0, t; }" : "=r"(a) : "l"(p));
    return a;
}
__device__ __forceinline__ uint16_t bfbits(__nv_bfloat16 h) { __nv_bfloat16_raw r = h; return r.x; }
__device__ __forceinline__ uint32_t pk2(__nv_bfloat16 a, __nv_bfloat16 b) {
    return (uint32_t)bfbits(a) | ((uint32_t)bfbits(b) << 16);
}
__device__ __forceinline__ float bflo(uint32_t u) { return __uint_as_float(u << 16); }
__device__ __forceinline__ float bfhi(uint32_t u) { return __uint_as_float(u & 0xFFFF0000u); }

__device__ __forceinline__ void cp16(uint32_t dst, const void* src) {
    asm volatile("cp.async.cg.shared.global [%0], [%1], 16;" :: "r"(dst), "l"(src));
}
#define CP_COMMIT() asm volatile("cp.async.commit_group;" ::: "memory")
#define CP_WAIT0()  asm volatile("cp.async.wait_group 0;" ::: "memory")
#define CP_WAIT1()  asm volatile("cp.async.wait_group 1;" ::: "memory")

__device__ __forceinline__ void ldsm4(uint32_t r[4], uint32_t a) {
    asm volatile("ldmatrix.sync.aligned.m8n8.x4.shared.b16 {%0,%1,%2,%3}, [%4];"
        : "=r"(r[0]), "=r"(r[1]), "=r"(r[2]), "=r"(r[3]) : "r"(a));
}
__device__ __forceinline__ void mma16816(float c[4], const uint32_t a[4], uint32_t b0, uint32_t b1) {
    asm volatile("mma.sync.aligned.m16n8k16.row.col.f32.bf16.bf16.f32 "
        "{%0,%1,%2,%3}, {%4,%5,%6,%7}, {%8,%9}, {%0,%1,%2,%3};"
        : "+f"(c[0]), "+f"(c[1]), "+f"(c[2]), "+f"(c[3])
        : "r"(a[0]), "r"(a[1]), "r"(a[2]), "r"(a[3]), "r"(b0), "r"(b1));
}

__device__ __forceinline__ float4 ldcg4(const float4* p) {
    float4 v;
    asm volatile("ld.global.cg.v4.f32 {%0,%1,%2,%3}, [%4];"
        : "=f"(v.x), "=f"(v.y), "=f"(v.z), "=f"(v.w) : "l"(p));
    return v;
}
__device__ __forceinline__ void stcg4(float4* p, float4 v) {
    asm volatile("st.global.cg.v4.f32 [%0], {%1,%2,%3,%4};"
        :: "l"(p), "f"(v.x), "f"(v.y), "f"(v.z), "f"(v.w));
}

// sense-reversing grid barrier with sleep-backoff poll;
// even total flips per launch -> self-resetting for graph replay
__device__ __forceinline__ void gbar(unsigned s) {
    __syncthreads();
    __threadfence();
    if (threadIdx.x == 0) {
        if (atomicAdd((unsigned*)&g_count0, 1u) == FGRID - 1) {
            g_count0 = 0;
            __threadfence();
            g_sense0 = s;
        } else {
            while (g_sense0 != s) { __nanosleep(64); }
        }
    }
    __syncthreads();
}

// one K=32 chunk of split-2 MMA, warp tile M32 x N32
__device__ __forceinline__ void mma_chunk32(uint32_t sb, int a_hi_off, int a_lo_off, int a_stride,
                                            int a_kcol, int w_hi_off, int w_lo_off,
                                            float acc[2][4][4], int wm, int wn, int lane) {
    const int arow = (lane & 15);
    const int asel = (lane >> 4) & 1;
    const int seg = lane >> 3;
    const int b_nrow = (seg >> 1) * 8 + (lane & 7);
    const int b_kofs = (seg & 1) * 8;
#pragma unroll
    for (int ks = 0; ks < 2; ks++) {
        const int k0a = a_kcol + ks * 16;
        const int k0w = ks * 16;
        uint32_t ah[2][4], al[2][4];
#pragma unroll
        for (int mi = 0; mi < 2; mi++) {
            const int row = wm * 32 + mi * 16 + arow;
            ldsm4(ah[mi], sb + a_hi_off + (row * a_stride + k0a + asel * 8) * 2);
            ldsm4(al[mi], sb + a_lo_off + (row * a_stride + k0a + asel * 8) * 2);
        }
#pragma unroll
        for (int ni2 = 0; ni2 < 2; ni2++) {
            const int nrow = wn * 32 + ni2 * 16 + b_nrow;
            uint32_t bh[4], bl[4];
            ldsm4(bh, sb + w_hi_off + (nrow * SA + k0w + b_kofs) * 2);
            ldsm4(bl, sb + w_lo_off + (nrow * SA + k0w + b_kofs) * 2);
#pragma unroll
            for (int h = 0; h < 2; h++) {
                const int ni = ni2 * 2 + h;
#pragma unroll
                for (int mi = 0; mi < 2; mi++) {
                    mma16816(acc[mi][ni], ah[mi], bh[2 * h], bh[2 * h + 1]);
                    mma16816(acc[mi][ni], ah[mi], bl[2 * h], bl[2 * h + 1]);
                    mma16816(acc[mi][ni], al[mi], bh[2 * h], bh[2 * h + 1]);
                }
            }
        }
    }
}

// ---------------- merged prep + hist (+ desc clear) ----------------
__global__ void histprep_kernel(const int* __restrict__ ei,
                                const float* __restrict__ w1, const float* __restrict__ b1,
                                const float* __restrict__ g1, const float* __restrict__ be1,
                                const float* __restrict__ m1, const float* __restrict__ v1,
                                const float* __restrict__ w2, const float* __restrict__ b2,
                                const float* __restrict__ g2, const float* __restrict__ be2,
                                const float* __restrict__ m2, const float* __restrict__ v2) {
    if (blockIdx.x < 128) {
        const int j = blockIdx.x;
        const float s1 = g1[j] * rsqrtf(v1[j] + EPSB);
        const float s2 = g2[j] * rsqrtf(v2[j] + EPSB);
        for (int k = threadIdx.x; k < 512; k += blockDim.x) {
            float w = s1 * w1[j * 512 + k];
            __nv_bfloat16 h = __float2bfloat16(w);
            g_w1hi[j * 512 + k] = h;
            g_w1lo[j * 512 + k] = __float2bfloat16(w - __bfloat162float(h));
        }
        for (int k = threadIdx.x; k < 128; k += blockDim.x) {
            float w = s2 * w2[j * 128 + k];
            __nv_bfloat16 h = __float2bfloat16(w);
            g_w2hi[j * 128 + k] = h;
            g_w2lo[j * 128 + k] = __float2bfloat16(w - __bfloat162float(h));
        }
        if (threadIdx.x == 0) {
            g_b1e[j] = s1 * (b1[j] - m1[j]) + be1[j];
            g_b2e[j] = s2 * (b2[j] - m2[j]) + be2[j];
        }
    } else {
        const int gt = (blockIdx.x - 128) * blockDim.x + threadIdx.x;
        if (gt < NBLK_SCAN) g_desc[gt] = 0ULL;
        if (gt < EE / 4) {
            int4 d = ((const int4*)(ei + EE))[gt];
            atomicAdd(&g_cnt[d.x], 1);
            atomicAdd(&g_cnt[d.y], 1);
            atomicAdd(&g_cnt[d.z], 1);
            atomicAdd(&g_cnt[d.w], 1);
        }
    }
}

// ---------------- decoupled-lookback scan (+ cnt re-zero) ----------------
__global__ __launch_bounds__(512) void scan_kernel() {
    __shared__ int s[512];
    __shared__ int s_run;
    const int tid = threadIdx.x, bid = blockIdx.x;
    const int idx = bid * 512 + tid;
    const int v = (idx < NN) ? g_cnt[idx] : 0;
    s[tid] = v;
    __syncthreads();
    for (int off = 1; off < 512; off <<= 1) {
        int t = (tid >= off) ? s[tid - off] : 0;
        __syncthreads();
        s[tid] += t;
        __syncthreads();
    }
    const int agg = s[511];
    if (tid == 0) {
        unsigned long long d = (bid == 0) ? ((2ULL << 32) | (unsigned)agg)
                                          : ((1ULL << 32) | (unsigned)agg);
        atomicExch(&g_desc[bid], d);
        if (bid == 0) s_run = 0;
    }
    if (bid > 0 && tid < 32) {
        int run = 0;
        int j = bid - 1;
        while (true) {
            int ridx = j - tid;
            unsigned long long d = (ridx >= 0) ? atomicAdd(&g_desc[ridx], 0ULL) : (2ULL << 32);
            int st = (int)(d >> 32);
            int val = (int)(d & 0xffffffffu);
            unsigned inv  = __ballot_sync(0xffffffffu, st == 0);
            unsigned incl = __ballot_sync(0xffffffffu, st == 2);
            int fInv  = inv  ? (__ffs(inv) - 1)  : 32;
            int fIncl = incl ? (__ffs(incl) - 1) : 32;
            if (fIncl < fInv) {
                int contrib = (tid <= fIncl) ? val : 0;
#pragma unroll
                for (int o = 16; o; o >>= 1) contrib += __shfl_xor_sync(0xffffffffu, contrib, o);
                run += contrib;
                break;
            } else {
                int contrib = (tid < fInv) ? val : 0;
#pragma unroll
                for (int o = 16; o; o >>= 1) contrib += __shfl_xor_sync(0xffffffffu, contrib, o);
                run += contrib;
                j -= fInv;
            }
        }
        if (tid == 0) {
            atomicExch(&g_desc[bid], (2ULL << 32) | (unsigned)(run + agg));
            s_run = run;
        }
    }
    __syncthreads();
    const int run = s_run;
    if (idx < NN) {
        int ex = run + s[tid] - v;
        g_rowptr[idx] = ex;
        g_wp[idx] = ex;
        g_dinv[idx] = rsqrtf((float)v + 1.0f);
        g_cnt[idx] = 0;
    }
    if (bid == NBLK_SCAN - 1 && tid == 511) g_rowptr[NN] = run + agg;
}

// ---------------- fused MLP (writes h0a and yA = dinv*h0; needs scan first) -------------
__global__ __launch_bounds__(256, 2) void mlp_kernel(const float* __restrict__ x,
                                                     const float* __restrict__ w3,
                                                     const float* __restrict__ b3) {
    extern __shared__ char smem[];
    const uint32_t sb = smem_u32(smem);
    __nv_bfloat16* H1hi = (__nv_bfloat16*)(smem + OFF_H1HI);
    __nv_bfloat16* H1lo = (__nv_bfloat16*)(smem + OFF_H1LO);
    float* part = (float*)(smem + OFF_PART);
    float* b1s = (float*)(smem + OFF_B1);
    float* b2s = (float*)(smem + OFF_B2);
    float* w3s = (float*)(smem + OFF_W3);
    float* b3s = (float*)(smem + OFF_B3);

    const int tid = threadIdx.x;
    const int wid = tid >> 5, lane = tid & 31;
    const int wm = wid & 1, wn = wid >> 1;
    const int lq = lane >> 2, lr = lane & 3;
    const long rbase = (long)blockIdx.x * TM;

    const int alrow = tid >> 2;
    const int alcol = (tid & 3) * 8;
    const long grow_ld = rbase + alrow;
    const float4* xrow = (grow_ld < NN) ? (const float4*)(x + grow_ld * 512 + alcol) : (const float4*)0;
    const uint32_t a_st = (uint32_t)(alrow * SA + alcol);
    const int wlrow = tid >> 1;
    const int wlcol = (tid & 1) * 16;
    const uint32_t w_st = (uint32_t)(wlrow * SA + wlcol);

    if (tid < 128) { b1s[tid] = g_b1e[tid]; b2s[tid] = g_b2e[tid]; }
    if (tid < 3)   { b3s[tid] = b3[tid]; }
    if (tid >= 128 && tid < 224) ((float4*)w3s)[tid - 128] = ((const float4*)w3)[tid - 128];

    float acc[2][4][4];
#pragma unroll
    for (int mi = 0; mi < 2; mi++)
#pragma unroll
        for (int ni = 0; ni < 4; ni++)
#pragma unroll
            for (int q = 0; q < 4; q++) acc[mi][ni][q] = 0.f;

    auto issue_w1 = [&](int c, int b) {
        const int k0 = c * 32;
        cp16(sb + WHI_OFF(b) + w_st * 2,      &g_w1hi[wlrow * 512 + k0 + wlcol]);
        cp16(sb + WHI_OFF(b) + w_st * 2 + 16, &g_w1hi[wlrow * 512 + k0 + wlcol + 8]);
        cp16(sb + WLO_OFF(b) + w_st * 2,      &g_w1lo[wlrow * 512 + k0 + wlcol]);
        cp16(sb + WLO_OFF(b) + w_st * 2 + 16, &g_w1lo[wlrow * 512 + k0 + wlcol + 8]);
    };
    auto issue_w2 = [&](int c, int b) {
        const int k0 = c * 32;
        cp16(sb + WHI_OFF(b) + w_st * 2,      &g_w2hi[wlrow * 128 + k0 + wlcol]);
        cp16(sb + WHI_OFF(b) + w_st * 2 + 16, &g_w2hi[wlrow * 128 + k0 + wlcol + 8]);
        cp16(sb + WLO_OFF(b) + w_st * 2,      &g_w2lo[wlrow * 128 + k0 + wlcol]);
        cp16(sb + WLO_OFF(b) + w_st * 2 + 16, &g_w2lo[wlrow * 128 + k0 + wlcol + 8]);
    };
    float4 xr[2];
    auto ldg_x = [&](int c) {
        const int k04 = c * 8 + (tid & 3) * 2;
        if (xrow) { xr[0] = ((const float4*)(x + grow_ld * 512))[k04];
                    xr[1] = ((const float4*)(x + grow_ld * 512))[k04 + 1]; }
        else { xr[0] = xr[1] = make_float4(0.f, 0.f, 0.f, 0.f); }
    };
    auto sts_x = [&](int b) {
        char* hbase = smem + AHI_OFF(b);
        char* lbase = smem + ALO_OFF(b);
#pragma unroll
        for (int i = 0; i < 2; i++) {
            float4 v = xr[i];
            __nv_bfloat16 hx = __float2bfloat16(v.x), hy = __float2bfloat16(v.y);
            __nv_bfloat16 hz = __float2bfloat16(v.z), hw = __float2bfloat16(v.w);
            __nv_bfloat16 lx = __float2bfloat16(v.x - __bfloat162float(hx));
            __nv_bfloat16 ly = __float2bfloat16(v.y - __bfloat162float(hy));
            __nv_bfloat16 lz = __float2bfloat16(v.z - __bfloat162float(hz));
            __nv_bfloat16 lw = __float2bfloat16(v.w - __bfloat162float(hw));
            uint32_t eo = (a_st + i * 4) * 2;
            *(uint2*)(hbase + eo) = make_uint2(pk2(hx, hy), pk2(hz, hw));
            *(uint2*)(lbase + eo) = make_uint2(pk2(lx, ly), pk2(lz, lw));
        }
    };

    // ===== GEMM1 =====
    ldg_x(0);
    issue_w1(0, 0);
    CP_COMMIT();
    sts_x(0);
    CP_WAIT0();
    __syncthreads();

#pragma unroll 1
    for (int c = 0; c < 16; c++) {
        const int buf = c & 1, nbuf = buf ^ 1;
        if (c < 15) {
            issue_w1(c + 1, nbuf);
            CP_COMMIT();
            ldg_x(c + 1);
        }
        mma_chunk32(sb, AHI_OFF(buf), ALO_OFF(buf), SA, 0, WHI_OFF(buf), WLO_OFF(buf),
                    acc, wm, wn, lane);
        if (c < 15) { sts_x(nbuf); CP_WAIT0(); }
        __syncthreads();
    }

    issue_w2(0, 0); CP_COMMIT();
    issue_w2(1, 1); CP_COMMIT();

    // ===== epilogue 1 =====
#pragma unroll
    for (int mi = 0; mi < 2; mi++) {
        const int r = wm * 32 + mi * 16 + lq;
#pragma unroll
        for (int ni = 0; ni < 4; ni++) {
            const int c = wn * 32 + ni * 8 + lr * 2;
            float* a = acc[mi][ni];
            float bb0 = b1s[c], bb1 = b1s[c + 1];
            float v0 = fmaxf(a[0] + bb0, 0.f), v1 = fmaxf(a[1] + bb1, 0.f);
            float v2 = fmaxf(a[2] + bb0, 0.f), v3 = fmaxf(a[3] + bb1, 0.f);
            __nv_bfloat16 h0 = __float2bfloat16(v0), h1 = __float2bfloat16(v1);
            __nv_bfloat16 h2 = __float2bfloat16(v2), h3 = __float2bfloat16(v3);
            *(uint32_t*)&H1hi[r * SH + c] = pk2(h0, h1);
            *(uint32_t*)&H1lo[r * SH + c] =
                pk2(__float2bfloat16(v0 - __bfloat162float(h0)), __float2bfloat16(v1 - __bfloat162float(h1)));
            *(uint32_t*)&H1hi[(r + 8) * SH + c] = pk2(h2, h3);
            *(uint32_t*)&H1lo[(r + 8) * SH + c] =
                pk2(__float2bfloat16(v2 - __bfloat162float(h2)), __float2bfloat16(v3 - __bfloat162float(h3)));
            a[0] = a[1] = a[2] = a[3] = 0.f;
        }
    }

    // ===== GEMM2 =====
    CP_WAIT1(); __syncthreads();
    mma_chunk32(sb, OFF_H1HI, OFF_H1LO, SH, 0, WHI_OFF(0), WLO_OFF(0), acc, wm, wn, lane);
    __syncthreads();
    issue_w2(2, 0); CP_COMMIT();
    CP_WAIT1(); __syncthreads();
    mma_chunk32(sb, OFF_H1HI, OFF_H1LO, SH, 32, WHI_OFF(1), WLO_OFF(1), acc, wm, wn, lane);
    __syncthreads();
    issue_w2(3, 1); CP_COMMIT();
    CP_WAIT1(); __syncthreads();
    mma_chunk32(sb, OFF_H1HI, OFF_H1LO, SH, 64, WHI_OFF(0), WLO_OFF(0), acc, wm, wn, lane);
    CP_WAIT0(); __syncthreads();
    mma_chunk32(sb, OFF_H1HI, OFF_H1LO, SH, 96, WHI_OFF(1), WLO_OFF(1), acc, wm, wn, lane);

    // ===== epilogue 2 =====
    float o[2][2][3];
#pragma unroll
    for (int mi = 0; mi < 2; mi++)
#pragma unroll
        for (int hf = 0; hf < 2; hf++) o[mi][hf][0] = o[mi][hf][1] = o[mi][hf][2] = 0.f;
#pragma unroll
    for (int mi = 0; mi < 2; mi++) {
        const int r = wm * 32 + mi * 16 + lq;
#pragma unroll
        for (int ni = 0; ni < 4; ni++) {
            const int c = wn * 32 + ni * 8 + lr * 2;
            const float w30 = w3s[c], w31 = w3s[c + 1];
            const float w40 = w3s[128 + c], w41 = w3s[128 + c + 1];
            const float w50 = w3s[256 + c], w51 = w3s[256 + c + 1];
            const float bb0 = b2s[c], bb1 = b2s[c + 1];
            const float* a = acc[mi][ni];
            {
                uint32_t hh = *(const uint32_t*)&H1hi[r * SH + c];
                uint32_t hl = *(const uint32_t*)&H1lo[r * SH + c];
                float g0 = bflo(hh) + bflo(hl) + fmaxf(a[0] + bb0, 0.f);
                float g1 = bfhi(hh) + bfhi(hl) + fmaxf(a[1] + bb1, 0.f);
                o[mi][0][0] = fmaf(g0, w30, fmaf(g1, w31, o[mi][0][0]));
                o[mi][0][1] = fmaf(g0, w40, fmaf(g1, w41, o[mi][0][1]));
                o[mi][0][2] = fmaf(g0, w50, fmaf(g1, w51, o[mi][0][2]));
            }
            {
                uint32_t hh = *(const uint32_t*)&H1hi[(r + 8) * SH + c];
                uint32_t hl = *(const uint32_t*)&H1lo[(r + 8) * SH + c];
                float g0 = bflo(hh) + bflo(hl) + fmaxf(a[2] + bb0, 0.f);
                float g1 = bfhi(hh) + bfhi(hl) + fmaxf(a[3] + bb1, 0.f);
                o[mi][1][0] = fmaf(g0, w30, fmaf(g1, w31, o[mi][1][0]));
                o[mi][1][1] = fmaf(g0, w40, fmaf(g1, w41, o[mi][1][1]));
                o[mi][1][2] = fmaf(g0, w50, fmaf(g1, w51, o[mi][1][2]));
            }
        }
    }
#pragma unroll
    for (int mi = 0; mi < 2; mi++)
#pragma unroll
        for (int hf = 0; hf < 2; hf++)
#pragma unroll
            for (int j = 0; j < 3; j++) {
                o[mi][hf][j] += __shfl_xor_sync(0xffffffffu, o[mi][hf][j], 1);
                o[mi][hf][j] += __shfl_xor_sync(0xffffffffu, o[mi][hf][j], 2);
            }
    if (lr == 0) {
#pragma unroll
        for (int mi = 0; mi < 2; mi++)
#pragma unroll
            for (int hf = 0; hf < 2; hf++) {
                const int r = wm * 32 + mi * 16 + lq + hf * 8;
                float* p = &part[(wn * 64 + r) * 3];
                p[0] = o[mi][hf][0]; p[1] = o[mi][hf][1]; p[2] = o[mi][hf][2];
            }
    }
    __syncthreads();
    if (tid < 64) {
        const long grow = rbase + tid;
        if (grow < NN) {
            float s0 = b3s[0], s1 = b3s[1], s2 = b3s[2];
#pragma unroll
            for (int w = 0; w < 4; w++) {
                s0 += part[(w * 64 + tid) * 3 + 0];
                s1 += part[(w * 64 + tid) * 3 + 1];
                s2 += part[(w * 64 + tid) * 3 + 2];
            }
            float dv = g_dinv[grow];
            g_h0a[grow] = make_float4(ALPHAF * s0, ALPHAF * s1, ALPHAF * s2, 0.f);
            g_yA[grow] = make_float4(dv * s0, dv * s1, dv * s2, 0.f);
        }
    }
}

// ---------------- persistent fused: scatter + 10x propagation + log_softmax -------------
// Propagation: 8-lane node groups, 4-way software-pipelined gathers.
__global__ __launch_bounds__(256, 6) void fused_graph_kernel(const int* __restrict__ ei,
                                                             float* __restrict__ out) {
    // phase 0: CSR scatter
    for (int e4 = blockIdx.x * blockDim.x + threadIdx.x; e4 < EE / 4; e4 += FGRID * 256) {
        int4 s = ((const int4*)ei)[e4];
        int4 d = ((const int4*)(ei + EE))[e4];
        g_col[atomicAdd(&g_wp[d.x], 1)] = s.x;
        g_col[atomicAdd(&g_wp[d.y], 1)] = s.y;
        g_col[atomicAdd(&g_wp[d.z], 1)] = s.z;
        g_col[atomicAdd(&g_wp[d.w], 1)] = s.w;
    }
    gbar(1u);

    const int ggroup = (blockIdx.x * 256 + threadIdx.x) / LPG;
    const int gl = threadIdx.x & (LPG - 1);
    const int ngroups = FGRID * 256 / LPG;

#pragma unroll 1
    for (int it = 0; it < KITER; it++) {
        const float4* yin = (it & 1) ? g_yB : g_yA;
        float4* yout = (it & 1) ? g_yA : g_yB;
#pragma unroll 1
        for (int node = ggroup; node < NN; node += ngroups) {
            const int s0 = __ldg(&g_rowptr[node]), s1 = __ldg(&g_rowptr[node + 1]);
            float4 self = ldcg4(&yin[node]);
            float4 h = __ldg(&g_h0a[node]);
            float dv = __ldg(&g_dinv[node]);
            float a0 = 0.f, a1 = 0.f, a2 = 0.f;
            int e = s0 + gl;
            // 4-way pipelined main loop: batch col loads, then 4 independent gathers
#pragma unroll 1
            for (; e + 3 * LPG < s1; e += 4 * LPG) {
                int c0 = __ldg(&g_col[e]);
                int c1 = __ldg(&g_col[e + LPG]);
                int c2 = __ldg(&g_col[e + 2 * LPG]);
                int c3 = __ldg(&g_col[e + 3 * LPG]);
                float4 v0 = ldcg4(&yin[c0]);
                float4 v1 = ldcg4(&yin[c1]);
                float4 v2 = ldcg4(&yin[c2]);
                float4 v3 = ldcg4(&yin[c3]);
                a0 += (v0.x + v1.x) + (v2.x + v3.x);
                a1 += (v0.y + v1.y) + (v2.y + v3.y);
                a2 += (v0.z + v1.z) + (v2.z + v3.z);
            }
#pragma unroll 1
            for (; e < s1; e += LPG) {
                float4 v = ldcg4(&yin[__ldg(&g_col[e])]);
                a0 += v.x; a1 += v.y; a2 += v.z;
            }
#pragma unroll
            for (int o = LPG / 2; o > 0; o >>= 1) {
                a0 += __shfl_xor_sync(0xffffffffu, a0, o);
                a1 += __shfl_xor_sync(0xffffffffu, a1, o);
                a2 += __shfl_xor_sync(0xffffffffu, a2, o);
            }
            if (gl == 0) {
                float c = (1.0f - ALPHAF) * dv;
                float z0 = c * (a0 + self.x) + h.x;
                float z1 = c * (a1 + self.y) + h.y;
                float z2 = c * (a2 + self.z) + h.z;
                if (it == KITER - 1) {
                    float m = fmaxf(z0, fmaxf(z1, z2));
                    float l = m + logf(expf(z0 - m) + expf(z1 - m) + expf(z2 - m));
                    out[3 * node + 0] = z0 - l;
                    out[3 * node + 1] = z1 - l;
                    out[3 * node + 2] = z2 - l;
                } else {
                    stcg4(&yout[node], make_float4(dv * z0, dv * z1, dv * z2, 0.f));
                }
            }
        }
        if (it < KITER - 1) gbar((unsigned)(it & 1));  // 9 + 1 (scatter) = 10 flips: even
    }
}

extern "C" void kernel_launch(void* const* d_in, const int* in_sizes, int n_in,
                              void* d_out, int out_size) {
    const float* x  = (const float*)d_in[0];
    const int* ei   = (const int*)d_in[1];
    const float* w1 = (const float*)d_in[2];
    const float* b1 = (const float*)d_in[3];
    const float* g1 = (const float*)d_in[4];
    const float* be1 = (const float*)d_in[5];
    const float* m1 = (const float*)d_in[6];
    const float* v1 = (const float*)d_in[7];
    const float* w2 = (const float*)d_in[8];
    const float* b2 = (const float*)d_in[9];
    const float* g2 = (const float*)d_in[10];
    const float* be2 = (const float*)d_in[11];
    const float* m2 = (const float*)d_in[12];
    const float* v2 = (const float*)d_in[13];
    const float* w3 = (const float*)d_in[14];
    const float* b3 = (const float*)d_in[15];
    float* out = (float*)d_out;

    cudaFuncSetAttribute(mlp_kernel, cudaFuncAttributeMaxDynamicSharedMemorySize, SMEM_MLP);

    // 4 kernels, single stream; fused_graph_kernel is the 4th (profiled slot)
    histprep_kernel<<<128 + (EE / 4 + 255) / 256, 256>>>(ei,
        w1, b1, g1, be1, m1, v1, w2, b2, g2, be2, m2, v2);               // 1 (prep+hist+desc)
    scan_kernel<<<NBLK_SCAN, 512>>>();                                   // 2 (rowptr/wp/dinv, cnt=0)
    mlp_kernel<<<NTILES, 256, SMEM_MLP>>>(x, w3, b3);                    // 3 (h0a, yA=dinv*h0)
    fused_graph_kernel<<<FGRID, 256>>>(ei, out);                         // 4 <- profiled
}